// round 1
// baseline (speedup 1.0000x reference)
#include <cuda_runtime.h>
#include <cstdint>
#include <cstdio>

#define NROWS 594880   // 55 * 64 * 169
#define NN    10816    // 64 * 169 (batch per timestep)
#define TSTEPS 55
#define HL    100

// ---------------- static device scratch (no allocations allowed) ------------
__device__ float g_act0[(size_t)NROWS * 30];
__device__ float g_act1[(size_t)NROWS * 30];
__device__ float g_xw [(size_t)NROWS * 400];   // reused by both LSTM layers
__device__ float g_hs1[(size_t)NROWS * HL];
__device__ float g_hs2[(size_t)NROWS * HL];
__device__ float g_c0 [NN * HL];
__device__ float g_c1 [NN * HL];

// ---------------- input transpose: [B,13,13,L,C] -> [(l*B+b)*169+pix, C] ----
__global__ void transpose_in(const float* __restrict__ x, float* __restrict__ y) {
    long idx = (long)blockIdx.x * blockDim.x + threadIdx.x;
    const long total = (long)NROWS * 6;           // 6 float4 per 24-channel row
    if (idx >= total) return;
    int  c4  = (int)(idx % 6);
    long row = idx / 6;                           // destination row
    int  pix = (int)(row % 169);
    long t1  = row / 169;
    int  b   = (int)(t1 % 64);
    int  l   = (int)(t1 / 64);
    long src = (((long)(b * 169 + pix)) * 55 + l) * 24 + c4 * 4;
    reinterpret_cast<float4*>(y)[row * 6 + c4] =
        *reinterpret_cast<const float4*>(x + src);
}

// ---------------- generic tiled fp32 GEMM: C = act(A[M,K]@B[K,N] (+bias)(+C))
template<int BM, int BN, int BK, int TM, int TN, bool RELU, bool ACC, bool BIAS>
__global__ void gemm_kernel(const float* __restrict__ A, const float* __restrict__ B,
                            const float* __restrict__ bias, float* __restrict__ C,
                            int M, int N, int K) {
    __shared__ float As[BK][BM + 4];
    __shared__ float Bs[BK][BN + 4];
    constexpr int THREADS = (BM / TM) * (BN / TN);
    const int tid  = threadIdx.x;
    const int tcol = tid % (BN / TN);
    const int trow = tid / (BN / TN);
    const int block_row = blockIdx.y * BM;
    const int block_col = blockIdx.x * BN;

    float acc[TM][TN];
    #pragma unroll
    for (int i = 0; i < TM; i++)
        #pragma unroll
        for (int j = 0; j < TN; j++) acc[i][j] = 0.f;

    for (int k0 = 0; k0 < K; k0 += BK) {
        #pragma unroll
        for (int i = tid; i < BM * BK; i += THREADS) {
            int r = i / BK, c = i % BK;
            int gr = block_row + r, gc = k0 + c;
            As[c][r] = (gr < M && gc < K) ? A[(size_t)gr * K + gc] : 0.f;
        }
        #pragma unroll
        for (int i = tid; i < BK * BN; i += THREADS) {
            int r = i / BN, c = i % BN;
            int gr = k0 + r, gc = block_col + c;
            Bs[r][c] = (gr < K && gc < N) ? B[(size_t)gr * N + gc] : 0.f;
        }
        __syncthreads();
        #pragma unroll
        for (int k = 0; k < BK; k++) {
            float a[TM], b[TN];
            #pragma unroll
            for (int i = 0; i < TM; i++) a[i] = As[k][trow * TM + i];
            #pragma unroll
            for (int j = 0; j < TN; j++) b[j] = Bs[k][tcol * TN + j];
            #pragma unroll
            for (int i = 0; i < TM; i++)
                #pragma unroll
                for (int j = 0; j < TN; j++) acc[i][j] += a[i] * b[j];
        }
        __syncthreads();
    }

    #pragma unroll
    for (int i = 0; i < TM; i++) {
        int gr = block_row + trow * TM + i;
        if (gr >= M) continue;
        #pragma unroll
        for (int j = 0; j < TN; j++) {
            int gc = block_col + tcol * TN + j;
            if (gc >= N) continue;
            float v = acc[i][j];
            if (BIAS) v += bias[gc];
            if (ACC)  v += C[(size_t)gr * N + gc];
            if (RELU) v = fmaxf(v, 0.f);
            C[(size_t)gr * N + gc] = v;
        }
    }
}

// ---------------- 5x5 SAME conv, 13x13x30 -> 13x13x30, ReLU -----------------
// Two images per block; each thread computes 1 pixel x 30 cout for both images
// so every broadcast weight LDS feeds 2 FMAs.
__global__ void conv5x5_relu(const float* __restrict__ in, const float* __restrict__ w,
                             const float* __restrict__ bias, float* __restrict__ out) {
    __shared__ float s_in[2][13 * 13 * 30];   // 40.5 KB
    __shared__ float s_w[900];                // one (ki,kj) slice [30ci][30co]
    const int img0 = blockIdx.x * 2;
    const int tid  = threadIdx.x;

    for (int i = tid; i < 2 * 5070; i += 256) {
        int which = i / 5070, off = i % 5070;
        s_in[which][off] = in[(size_t)(img0 + which) * 5070 + off];
    }

    float acc0[30], acc1[30];
    #pragma unroll
    for (int co = 0; co < 30; co++) { acc0[co] = 0.f; acc1[co] = 0.f; }

    const int pix = tid;            // active when < 169
    const int pi = pix / 13, pj = pix % 13;

    for (int ki = 0; ki < 5; ki++) {
        for (int kj = 0; kj < 5; kj++) {
            __syncthreads();        // also covers initial input load on 1st iter
            for (int i = tid; i < 900; i += 256)
                s_w[i] = w[(size_t)(ki * 5 + kj) * 900 + i];
            __syncthreads();
            int ii = pi + ki - 2, jj = pj + kj - 2;
            if (pix < 169 && ii >= 0 && ii < 13 && jj >= 0 && jj < 13) {
                int base = (ii * 13 + jj) * 30;
                #pragma unroll
                for (int ci = 0; ci < 30; ci++) {
                    float a0 = s_in[0][base + ci];
                    float a1 = s_in[1][base + ci];
                    const float* wr = &s_w[ci * 30];
                    #pragma unroll
                    for (int co = 0; co < 30; co++) {
                        float wv = wr[co];
                        acc0[co] += a0 * wv;
                        acc1[co] += a1 * wv;
                    }
                }
            }
        }
    }

    if (pix < 169) {
        #pragma unroll
        for (int co = 0; co < 30; co++) {
            float bv = bias[co];
            out[(size_t)img0 * 5070 + pix * 30 + co]       = fmaxf(acc0[co] + bv, 0.f);
            out[(size_t)(img0 + 1) * 5070 + pix * 30 + co] = fmaxf(acc1[co] + bv, 0.f);
        }
    }
}

// ---------------- LSTM gate elementwise (TF gate order i,j,f,o) -------------
__device__ __forceinline__ float sigm(float x) { return 1.f / (1.f + expf(-x)); }

__global__ void lstm_gate(const float* __restrict__ z, const float* __restrict__ c_prev,
                          float* __restrict__ c_out, float* __restrict__ h_out) {
    int idx = blockIdx.x * blockDim.x + threadIdx.x;
    if (idx >= NN * HL) return;
    int n = idx / HL, u = idx - n * HL;
    const float* zr = z + (size_t)n * 400;
    float gi = zr[u];
    float gj = zr[u + 100];
    float gf = zr[u + 200];
    float go = zr[u + 300];
    float cp = c_prev ? c_prev[idx] : 0.f;
    float c  = sigm(gf + 1.f) * cp + sigm(gi) * tanhf(gj);
    float h  = sigm(go) * tanhf(c);
    c_out[idx] = c;
    h_out[idx] = h;
}

// ---------------- final 1x1 conv (100 -> 1) + output transpose --------------
// out[b,i,j,l] = dot(hs2[l, b*169+pix], we) + be   ->  out flat = n*55 + l
__global__ void final_proj(const float* __restrict__ hs2, const float* __restrict__ we,
                           const float* __restrict__ be, float* __restrict__ out) {
    long r = (long)blockIdx.x * blockDim.x + threadIdx.x;
    if (r >= (long)NROWS) return;
    int n = (int)(r % NN);
    int l = (int)(r / NN);
    const float4* row = reinterpret_cast<const float4*>(hs2 + (size_t)r * HL);
    const float4* wv  = reinterpret_cast<const float4*>(we);
    float acc = 0.f;
    #pragma unroll
    for (int i = 0; i < 25; i++) {
        float4 v = row[i], w = wv[i];
        acc += v.x * w.x + v.y * w.y + v.z * w.z + v.w * w.w;
    }
    out[(size_t)n * 55 + l] = acc + be[0];
}

// ---------------- host-side launchers ---------------------------------------
template<bool RELU, bool ACC, bool BIAS>
static void gemm_small(const float* A, const float* B, const float* bias, float* C,
                       int M, int N, int K) {
    dim3 grid((N + 31) / 32, (M + 127) / 128);
    gemm_kernel<128, 32, 16, 4, 4, RELU, ACC, BIAS><<<grid, 256>>>(A, B, bias, C, M, N, K);
}

template<bool RELU, bool ACC, bool BIAS>
static void gemm_big(const float* A, const float* B, const float* bias, float* C,
                     int M, int N, int K) {
    dim3 grid((N + 63) / 64, (M + 127) / 128);
    gemm_kernel<128, 64, 16, 8, 4, RELU, ACC, BIAS><<<grid, 256>>>(A, B, bias, C, M, N, K);
}

static void run_lstm(const float* X, int D, const float* W, const float* bias,
                     float* xw, float* hs, float* c0, float* c1) {
    // bulk x-projection for all timesteps: xw = X @ W[0:D] + bias
    gemm_big<false, false, true>(X, W, bias, xw, NROWS, 400, D);
    const int gb = (NN * HL + 255) / 256;
    // t = 0: h_prev = 0, c_prev = 0 -> recurrent GEMM is a no-op
    lstm_gate<<<gb, 256>>>(xw, nullptr, c0, hs);
    for (int t = 1; t < TSTEPS; t++) {
        gemm_big<false, true, false>(hs + (size_t)(t - 1) * NN * HL,
                                     W + (size_t)D * 400, nullptr,
                                     xw + (size_t)t * NN * 400, NN, 400, HL);
        float* cp = (t & 1) ? c0 : c1;
        float* cn = (t & 1) ? c1 : c0;
        lstm_gate<<<gb, 256>>>(xw + (size_t)t * NN * 400, cp, cn,
                               hs + (size_t)t * NN * HL);
    }
}

extern "C" void kernel_launch(void* const* d_in, const int* in_sizes, int n_in,
                              void* d_out, int out_size) {
    (void)in_sizes; (void)n_in; (void)out_size;
    const float* x = (const float*)d_in[0];
    const float* w1[4] = {(const float*)d_in[1], (const float*)d_in[3],
                          (const float*)d_in[5], (const float*)d_in[7]};
    const float* b1[4] = {(const float*)d_in[2], (const float*)d_in[4],
                          (const float*)d_in[6], (const float*)d_in[8]};
    const float* w2[4] = {(const float*)d_in[9],  (const float*)d_in[11],
                          (const float*)d_in[13], (const float*)d_in[15]};
    const float* b2[4] = {(const float*)d_in[10], (const float*)d_in[12],
                          (const float*)d_in[14], (const float*)d_in[16]};
    const float* lw1 = (const float*)d_in[17];
    const float* lb1 = (const float*)d_in[18];
    const float* lw2 = (const float*)d_in[19];
    const float* lb2 = (const float*)d_in[20];
    const float* we  = (const float*)d_in[21];
    const float* be  = (const float*)d_in[22];
    float* out = (float*)d_out;

    void *p0, *p1, *pxw, *ph1, *ph2, *pc0, *pc1;
    cudaGetSymbolAddress(&p0,  g_act0);
    cudaGetSymbolAddress(&p1,  g_act1);
    cudaGetSymbolAddress(&pxw, g_xw);
    cudaGetSymbolAddress(&ph1, g_hs1);
    cudaGetSymbolAddress(&ph2, g_hs2);
    cudaGetSymbolAddress(&pc0, g_c0);
    cudaGetSymbolAddress(&pc1, g_c1);
    float* act0 = (float*)p0;
    float* act1 = (float*)p1;
    float* xw   = (float*)pxw;
    float* hs1  = (float*)ph1;
    float* hs2  = (float*)ph2;
    float* c0   = (float*)pc0;
    float* c1   = (float*)pc1;

    // 1) input transpose -> act0 as [NROWS, 24]
    {
        long total = (long)NROWS * 6;
        transpose_in<<<(unsigned)((total + 255) / 256), 256>>>(x, act0);
    }

    // 2) four 1x1 convs (GEMMs), ReLU
    gemm_small<true, false, true>(act0, w1[0], b1[0], act1, NROWS, 30, 24);
    gemm_small<true, false, true>(act1, w1[1], b1[1], act0, NROWS, 30, 30);
    gemm_small<true, false, true>(act0, w1[2], b1[2], act1, NROWS, 30, 30);
    gemm_small<true, false, true>(act1, w1[3], b1[3], act0, NROWS, 30, 30);

    // 3) four 5x5 SAME convs, ReLU (3520 images, 2 per block)
    conv5x5_relu<<<1760, 256>>>(act0, w2[0], b2[0], act1);
    conv5x5_relu<<<1760, 256>>>(act1, w2[1], b2[1], act0);
    conv5x5_relu<<<1760, 256>>>(act0, w2[2], b2[2], act1);
    conv5x5_relu<<<1760, 256>>>(act1, w2[3], b2[3], act0);

    // 4) LSTM layer 1 (input dim 30), layer 2 (input dim 100)
    run_lstm(act0, 30,  lw1, lb1, xw, hs1, c0, c1);
    run_lstm(hs1, 100, lw2, lb2, xw, hs2, c0, c1);

    // 5) final 1x1 conv (100->1) fused with output transpose
    final_proj<<<(NROWS + 255) / 256, 256>>>(hs2, we, be, out);
}

// round 2
// speedup vs baseline: 1.3302x; 1.3302x over previous
#include <cuda_runtime.h>
#include <cstdint>
#include <cstdio>

#define NROWS 594880   // 55 * 64 * 169
#define NN    10816    // 64 * 169 (batch per timestep)
#define TSTEPS 55
#define HL    100
#define NIMG  3520     // 55 * 64 images of 13x13
#define RPB   74       // LSTM rows per block (padded to 80)
#define SHP   82       // padded row stride for s_h

typedef unsigned long long ull;

// ---------------- f32x2 packed-math helpers (sm_103a FFMA2) -----------------
__device__ __forceinline__ ull pk2(float lo, float hi) {
    ull r; asm("mov.b64 %0,{%1,%2};" : "=l"(r) : "f"(lo), "f"(hi)); return r;
}
__device__ __forceinline__ void upk2(ull v, float& lo, float& hi) {
    asm("mov.b64 {%0,%1},%2;" : "=f"(lo), "=f"(hi) : "l"(v));
}
__device__ __forceinline__ void fma2(ull& d, ull a, ull b) {
    asm("fma.rn.f32x2 %0,%1,%2,%3;" : "=l"(d) : "l"(a), "l"(b), "l"(d));
}

__device__ __forceinline__ float sigm(float x) {
    return __fdividef(1.f, 1.f + __expf(-x));
}
__device__ __forceinline__ float tanha(float x) {
    return __fdividef(2.f, 1.f + __expf(-2.f * x)) - 1.f;
}

// ---------------- static device scratch (no allocations allowed) ------------
__device__ float g_act0[(size_t)NROWS * 30];
__device__ float g_act1[(size_t)NROWS * 30];
__device__ float g_xw [(size_t)NROWS * 400];
__device__ float g_hs1[(size_t)NROWS * HL];
__device__ float g_hs2[(size_t)NROWS * HL];
__device__ float g_c0 [NN * HL];
__device__ float g_c1 [NN * HL];

// ---------------- input transpose -------------------------------------------
__global__ void transpose_in(const float* __restrict__ x, float* __restrict__ y) {
    long idx = (long)blockIdx.x * blockDim.x + threadIdx.x;
    const long total = (long)NROWS * 6;
    if (idx >= total) return;
    int  c4  = (int)(idx % 6);
    long row = idx / 6;
    int  pix = (int)(row % 169);
    long t1  = row / 169;
    int  b   = (int)(t1 % 64);
    int  l   = (int)(t1 / 64);
    long src = (((long)(b * 169 + pix)) * 55 + l) * 24 + c4 * 4;
    reinterpret_cast<float4*>(y)[row * 6 + c4] =
        *reinterpret_cast<const float4*>(x + src);
}

// ---------------- FFMA2 GEMM: C = act(A[M,K]@B[K,N] + bias) -----------------
// Full-K resident smem. A transposed in smem (row pairs -> f32x2 acc),
// B pre-duplicated ({b,b}) so FFMA2 broadcasts need no per-use movs.
template<int BM, int BN, int K, int TM, int TN, bool RELU, bool BIAS>
__global__ __launch_bounds__((BM / TM) * (BN / TN))
void gemm2(const float* __restrict__ A, const float* __restrict__ B,
           const float* __restrict__ bias, float* __restrict__ C,
           int M, int N) {
    extern __shared__ float sm[];
    float* As = sm;                               // [K][BM+2]
    ull*   Bs = (ull*)(sm + K * (BM + 2));        // [K][BN] duplicated
    constexpr int CT = BN / TN;
    constexpr int THREADS = (BM / TM) * CT;
    const int tid = threadIdx.x;
    const int tc = tid % CT;
    const int tr = tid / CT;
    const long row0 = (long)blockIdx.y * BM;
    const int  col0 = blockIdx.x * BN;

    for (int idx = tid; idx < BM * K; idx += THREADS) {
        int r = idx / K, k = idx - r * K;
        long gr = row0 + r;
        As[k * (BM + 2) + r] = (gr < M) ? A[gr * K + k] : 0.f;
    }
    for (int idx = tid; idx < K * BN; idx += THREADS) {
        int k = idx / BN, n = idx - k * BN;
        float v = B[(size_t)k * N + col0 + n];
        Bs[k * BN + n] = pk2(v, v);
    }
    __syncthreads();

    ull acc[TM / 2][TN];
    #pragma unroll
    for (int i = 0; i < TM / 2; i++)
        #pragma unroll
        for (int j = 0; j < TN; j++) acc[i][j] = 0ull;

    #pragma unroll 5
    for (int k = 0; k < K; k++) {
        ull a[TM / 2], b[TN];
        #pragma unroll
        for (int i = 0; i < TM / 2; i++)
            a[i] = *reinterpret_cast<const ull*>(&As[k * (BM + 2) + tr * TM + 2 * i]);
        #pragma unroll
        for (int j = 0; j < TN; j++) b[j] = Bs[k * BN + tc * TN + j];
        #pragma unroll
        for (int i = 0; i < TM / 2; i++)
            #pragma unroll
            for (int j = 0; j < TN; j++) fma2(acc[i][j], a[i], b[j]);
    }

    #pragma unroll
    for (int i = 0; i < TM / 2; i++) {
        long r0 = row0 + tr * TM + 2 * i;
        #pragma unroll
        for (int j = 0; j < TN; j++) {
            int col = col0 + tc * TN + j;
            float lo, hi;
            upk2(acc[i][j], lo, hi);
            if (BIAS) { float bv = bias[col]; lo += bv; hi += bv; }
            if (RELU) { lo = fmaxf(lo, 0.f); hi = fmaxf(hi, 0.f); }
            if (r0 < M)     C[(size_t)r0 * N + col]       = lo;
            if (r0 + 1 < M) C[(size_t)(r0 + 1) * N + col] = hi;
        }
    }
}

// ---------------- 5x5 SAME conv, FFMA2, 3 images/block ----------------------
// smem: zero-padded input [3][17][17][30] + full weights [25][30][30].
// Thread = (img, pixel-pair): acc packed over cout pairs (w LDS.64 natural).
__global__ __launch_bounds__(256, 1)
void conv5x5_f2(const float* __restrict__ in, const float* __restrict__ w,
                const float* __restrict__ bias, float* __restrict__ out) {
    extern __shared__ float sm[];
    const int SIN1 = 17 * 17 * 30;   // 8670
    float* sin = sm;
    float* sw  = sm + 3 * SIN1;

    const int tid  = threadIdx.x;
    const int img0 = blockIdx.x * 3;

    for (int i = tid; i < 3 * SIN1; i += 256) sin[i] = 0.f;
    __syncthreads();
    for (int i = tid; i < 22500; i += 256) sw[i] = w[i];
    for (int idx = tid; idx < 3 * 169 * 30; idx += 256) {
        int img = idx / 5070, rem = idx % 5070;
        int p = rem / 30, ci = rem % 30;
        if (img0 + img < NIMG)
            sin[img * SIN1 + ((p / 13 + 2) * 17 + (p % 13 + 2)) * 30 + ci] =
                in[(size_t)(img0 + img) * 5070 + rem];
    }
    __syncthreads();

    const int q   = tid;
    const int img = q / 85;
    const int pr  = q % 85;
    const bool active = (tid < 255) && (img0 + img < NIMG);

    if (active) {
        const int p0 = 2 * pr, p1 = 2 * pr + 1;     // p1 may be 169 (pad)
        const int pi0 = p0 / 13, pj0 = p0 % 13;
        const int pi1 = p1 / 13, pj1 = p1 % 13;     // p1=169 -> pi1=13 reads pad rows
        const float* base = sin + img * SIN1;

        ull acc0[15], acc1[15];
        #pragma unroll
        for (int c = 0; c < 15; c++) { acc0[c] = 0ull; acc1[c] = 0ull; }

        #pragma unroll
        for (int ki = 0; ki < 5; ki++) {
            #pragma unroll
            for (int kj = 0; kj < 5; kj++) {
                const int o0 = ((pi0 + ki) * 17 + pj0 + kj) * 30;
                const int o1 = ((pi1 + ki) * 17 + pj1 + kj) * 30;
                const float* wr = sw + (ki * 5 + kj) * 900;
                #pragma unroll 2
                for (int ci = 0; ci < 30; ci++) {
                    float a0 = base[o0 + ci];
                    float a1 = base[o1 + ci];
                    ull d0 = pk2(a0, a0);
                    ull d1 = pk2(a1, a1);
                    const ull* w2 = reinterpret_cast<const ull*>(&wr[ci * 30]);
                    #pragma unroll
                    for (int c = 0; c < 15; c++) {
                        ull wv = w2[c];
                        fma2(acc0[c], d0, wv);
                        fma2(acc1[c], d1, wv);
                    }
                }
            }
        }

        float* o0p = out + (size_t)(img0 + img) * 5070 + p0 * 30;
        float* o1p = out + (size_t)(img0 + img) * 5070 + p1 * 30;
        #pragma unroll
        for (int c = 0; c < 15; c++) {
            float b0 = bias[2 * c], b1 = bias[2 * c + 1];
            float lo, hi;
            upk2(acc0[c], lo, hi);
            o0p[2 * c]     = fmaxf(lo + b0, 0.f);
            o0p[2 * c + 1] = fmaxf(hi + b1, 0.f);
            if (p1 < 169) {
                upk2(acc1[c], lo, hi);
                o1p[2 * c]     = fmaxf(lo + b0, 0.f);
                o1p[2 * c + 1] = fmaxf(hi + b1, 0.f);
            }
        }
    }
}

// ---------------- fused LSTM step: z = xw[t] + h_prev@Wh -> gates -> c,h ----
// grid=147 (1 wave), 512 threads, smem: Wh [100][400] + h_prev^T [100][82pad].
// Thread = (unit-pair ut, row-group rt): acc[8 rows][4 gates] packed over the
// unit pair (Wh pairs adjacent -> natural LDS.64, a scalar dup'd).
__global__ __launch_bounds__(512, 1)
void lstm_step(const float* __restrict__ xw_t, const float* __restrict__ h_prev,
               const float* __restrict__ c_prev, const float* __restrict__ Wh,
               float* __restrict__ c_out, float* __restrict__ h_out, int first) {
    extern __shared__ float sm[];
    float* sW = sm;            // [100*400]
    float* sh = sm + 40000;    // [100][SHP]
    const int tid  = threadIdx.x;
    const int row0 = blockIdx.x * RPB;

    if (!first) {
        for (int i = tid; i < 40000; i += 512) sW[i] = Wh[i];
        for (int i = tid; i < 8000; i += 512) {
            int r = i / 100, k = i - r * 100;
            int gr = row0 + r;
            sh[k * SHP + r] = (r < RPB && gr < NN) ? h_prev[(size_t)gr * 100 + k] : 0.f;
        }
        __syncthreads();
    }

    const int ut = tid % 50;       // unit pair: units 2ut, 2ut+1
    const int rt = tid / 50;       // 0..10 (active < 10)
    const bool act = tid < 500;
    const int u0 = 2 * ut;

    ull acc[8][4];
    #pragma unroll
    for (int j = 0; j < 8; j++) {
        int r = rt * 8 + j, gr = row0 + r;
        bool v = act && r < RPB && gr < NN;
        #pragma unroll
        for (int g = 0; g < 4; g++)
            acc[j][g] = v ? *reinterpret_cast<const ull*>(&xw_t[(size_t)gr * 400 + g * 100 + u0])
                          : 0ull;
    }

    if (!first) {
        #pragma unroll 2
        for (int k = 0; k < 100; k++) {
            ull wq[4];
            #pragma unroll
            for (int g = 0; g < 4; g++)
                wq[g] = *reinterpret_cast<const ull*>(&sW[k * 400 + g * 100 + u0]);
            #pragma unroll
            for (int j = 0; j < 8; j++) {
                float av = sh[k * SHP + rt * 8 + j];
                ull ad = pk2(av, av);
                #pragma unroll
                for (int g = 0; g < 4; g++) fma2(acc[j][g], ad, wq[g]);
            }
        }
    }

    #pragma unroll
    for (int j = 0; j < 8; j++) {
        int r = rt * 8 + j, gr = row0 + r;
        if (act && r < RPB && gr < NN) {
            float cpx = 0.f, cpy = 0.f;
            if (!first) {
                float2 cp = *reinterpret_cast<const float2*>(&c_prev[(size_t)gr * 100 + u0]);
                cpx = cp.x; cpy = cp.y;
            }
            float i0, i1, j0, j1, f0, f1, o0, o1;
            upk2(acc[j][0], i0, i1);
            upk2(acc[j][1], j0, j1);
            upk2(acc[j][2], f0, f1);
            upk2(acc[j][3], o0, o1);
            float c0 = sigm(f0 + 1.f) * cpx + sigm(i0) * tanha(j0);
            float c1 = sigm(f1 + 1.f) * cpy + sigm(i1) * tanha(j1);
            float h0 = sigm(o0) * tanha(c0);
            float h1 = sigm(o1) * tanha(c1);
            *reinterpret_cast<float2*>(&c_out[(size_t)gr * 100 + u0]) = make_float2(c0, c1);
            *reinterpret_cast<float2*>(&h_out[(size_t)gr * 100 + u0]) = make_float2(h0, h1);
        }
    }
}

// ---------------- final 1x1 conv (100 -> 1) + output transpose --------------
__global__ void final_proj(const float* __restrict__ hs2, const float* __restrict__ we,
                           const float* __restrict__ be, float* __restrict__ out) {
    long r = (long)blockIdx.x * blockDim.x + threadIdx.x;
    if (r >= (long)NROWS) return;
    int n = (int)(r % NN);
    int l = (int)(r / NN);
    const float4* row = reinterpret_cast<const float4*>(hs2 + (size_t)r * HL);
    const float4* wv  = reinterpret_cast<const float4*>(we);
    float acc = 0.f;
    #pragma unroll
    for (int i = 0; i < 25; i++) {
        float4 v = row[i], w = wv[i];
        acc += v.x * w.x + v.y * w.y + v.z * w.z + v.w * w.w;
    }
    out[(size_t)n * 55 + l] = acc + be[0];
}

// ---------------- host side -------------------------------------------------
static void run_lstm2(const float* X, int D, const float* W, const float* b,
                      float* xw, float* hs, float* c0, float* c1) {
    // bulk x-projection: xw = X @ W[0:D] + b   (N=400)
    if (D == 30) {
        size_t smem = 30 * 130 * 4 + 30 * 100 * 8;
        gemm2<128, 100, 30, 8, 5, false, true>
            <<<dim3(4, 4648), 320, smem>>>(X, W, b, xw, NROWS, 400);
    } else {
        size_t smem = 100 * 130 * 4 + 100 * 100 * 8;
        gemm2<128, 100, 100, 8, 5, false, true>
            <<<dim3(4, 4648), 320, smem>>>(X, W, b, xw, NROWS, 400);
    }
    const float* Wh = W + (size_t)D * 400;
    const size_t lsm = (40000 + 100 * SHP) * sizeof(float);
    float* cbuf[2] = {c0, c1};
    const float* cp = nullptr;
    for (int t = 0; t < TSTEPS; t++) {
        float* cn = cbuf[t & 1];
        lstm_step<<<147, 512, lsm>>>(xw + (size_t)t * NN * 400,
                                     t ? hs + (size_t)(t - 1) * NN * HL : nullptr,
                                     cp, Wh, cn, hs + (size_t)t * NN * HL,
                                     t == 0 ? 1 : 0);
        cp = cn;
    }
}

extern "C" void kernel_launch(void* const* d_in, const int* in_sizes, int n_in,
                              void* d_out, int out_size) {
    (void)in_sizes; (void)n_in; (void)out_size;
    const float* x = (const float*)d_in[0];
    const float* w1[4] = {(const float*)d_in[1], (const float*)d_in[3],
                          (const float*)d_in[5], (const float*)d_in[7]};
    const float* b1[4] = {(const float*)d_in[2], (const float*)d_in[4],
                          (const float*)d_in[6], (const float*)d_in[8]};
    const float* w2[4] = {(const float*)d_in[9],  (const float*)d_in[11],
                          (const float*)d_in[13], (const float*)d_in[15]};
    const float* b2[4] = {(const float*)d_in[10], (const float*)d_in[12],
                          (const float*)d_in[14], (const float*)d_in[16]};
    const float* lw1 = (const float*)d_in[17];
    const float* lb1 = (const float*)d_in[18];
    const float* lw2 = (const float*)d_in[19];
    const float* lb2 = (const float*)d_in[20];
    const float* we  = (const float*)d_in[21];
    const float* be  = (const float*)d_in[22];
    float* out = (float*)d_out;

    void *p0, *p1, *pxw, *ph1, *ph2, *pc0, *pc1;
    cudaGetSymbolAddress(&p0,  g_act0);
    cudaGetSymbolAddress(&p1,  g_act1);
    cudaGetSymbolAddress(&pxw, g_xw);
    cudaGetSymbolAddress(&ph1, g_hs1);
    cudaGetSymbolAddress(&ph2, g_hs2);
    cudaGetSymbolAddress(&pc0, g_c0);
    cudaGetSymbolAddress(&pc1, g_c1);
    float* act0 = (float*)p0;
    float* act1 = (float*)p1;
    float* xw   = (float*)pxw;
    float* hs1  = (float*)ph1;
    float* hs2  = (float*)ph2;
    float* c0   = (float*)pc0;
    float* c1   = (float*)pc1;

    // opt-in large dynamic smem (idempotent, cheap)
    cudaFuncSetAttribute(conv5x5_f2, cudaFuncAttributeMaxDynamicSharedMemorySize, 194040);
    cudaFuncSetAttribute(lstm_step,  cudaFuncAttributeMaxDynamicSharedMemorySize,
                         (int)((40000 + 100 * SHP) * sizeof(float)));
    cudaFuncSetAttribute((const void*)gemm2<128, 100, 100, 8, 5, false, true>,
                         cudaFuncAttributeMaxDynamicSharedMemorySize, 132000);

    // 1) input transpose
    {
        long total = (long)NROWS * 6;
        transpose_in<<<(unsigned)((total + 255) / 256), 256>>>(x, act0);
    }

    // 2) four 1x1 convs (FFMA2 GEMMs, full-K smem)
    {
        size_t s24 = 24 * 130 * 4 + 24 * 30 * 8;
        size_t s30 = 30 * 130 * 4 + 30 * 30 * 8;
        gemm2<128, 30, 24, 8, 2, true, true><<<dim3(1, 4648), 240, s24>>>(act0, w1[0], b1[0], act1, NROWS, 30);
        gemm2<128, 30, 30, 8, 2, true, true><<<dim3(1, 4648), 240, s30>>>(act1, w1[1], b1[1], act0, NROWS, 30);
        gemm2<128, 30, 30, 8, 2, true, true><<<dim3(1, 4648), 240, s30>>>(act0, w1[2], b1[2], act1, NROWS, 30);
        gemm2<128, 30, 30, 8, 2, true, true><<<dim3(1, 4648), 240, s30>>>(act1, w1[3], b1[3], act0, NROWS, 30);
    }

    // 3) four 5x5 SAME convs (FFMA2, 3 imgs/block)
    {
        const int grid = (NIMG + 2) / 3;   // 1174
        conv5x5_f2<<<grid, 256, 194040>>>(act0, w2[0], b2[0], act1);
        conv5x5_f2<<<grid, 256, 194040>>>(act1, w2[1], b2[1], act0);
        conv5x5_f2<<<grid, 256, 194040>>>(act0, w2[2], b2[2], act1);
        conv5x5_f2<<<grid, 256, 194040>>>(act1, w2[3], b2[3], act0);
    }

    // 4) LSTM layers (fused per-step kernels)
    run_lstm2(act0, 30,  lw1, lb1, xw, hs1, c0, c1);
    run_lstm2(hs1, 100, lw2, lb2, xw, hs2, c0, c1);

    // 5) final projection + output transpose
    final_proj<<<(NROWS + 255) / 256, 256>>>(hs2, we, be, out);
}

// round 3
// speedup vs baseline: 1.4117x; 1.0613x over previous
#include <cuda_runtime.h>
#include <cstdint>

#define NROWS 594880   // 55 * 64 * 169
#define NN    10816    // 64 * 169 rows per timestep
#define TSTEPS 55
#define HL    100
#define NIMG  3520     // 55 * 64 images of 13x13

typedef unsigned long long ull;

// ---------------- f32x2 packed-math helpers (sm_103a FFMA2) -----------------
__device__ __forceinline__ ull pk2(float lo, float hi) {
    ull r; asm("mov.b64 %0,{%1,%2};" : "=l"(r) : "f"(lo), "f"(hi)); return r;
}
__device__ __forceinline__ void upk2(ull v, float& lo, float& hi) {
    asm("mov.b64 {%0,%1},%2;" : "=f"(lo), "=f"(hi) : "l"(v));
}
__device__ __forceinline__ void fma2(ull& d, ull a, ull b) {
    asm("fma.rn.f32x2 %0,%1,%2,%3;" : "=l"(d) : "l"(a), "l"(b), "l"(d));
}

__device__ __forceinline__ float sigm(float x) {
    return __fdividef(1.f, 1.f + __expf(-x));
}
__device__ __forceinline__ float tanha(float x) {
    return __fdividef(2.f, 1.f + __expf(-2.f * x)) - 1.f;
}

// ---------------- static device scratch -------------------------------------
__device__ float g_act0[(size_t)NROWS * 30];
__device__ float g_act1[(size_t)NROWS * 30];
__device__ float g_xw [(size_t)NROWS * 400];
__device__ float g_hs1[(size_t)NROWS * HL];
__device__ float g_hs2[(size_t)NROWS * HL];

// ---------------- input transpose: [B,13,13,L,C] -> [(l*64+b)*169+pix, 24] --
__global__ void transpose_in(const float* __restrict__ x, float* __restrict__ y) {
    long idx = (long)blockIdx.x * blockDim.x + threadIdx.x;
    const long total = (long)NROWS * 6;
    if (idx >= total) return;
    int  c4  = (int)(idx % 6);
    long row = idx / 6;
    int  pix = (int)(row % 169);
    long t1  = row / 169;
    int  b   = (int)(t1 % 64);
    int  l   = (int)(t1 / 64);
    long src = (((long)(b * 169 + pix)) * 55 + l) * 24 + c4 * 4;
    reinterpret_cast<float4*>(y)[row * 6 + c4] =
        *reinterpret_cast<const float4*>(x + src);
}

// ---------------- FFMA2 GEMM, LDS-balanced ----------------------------------
// BM=256 rows; thread = (tc col-group of 10, tr row-lane). 8 strided rows x
// 5 col-pairs per thread. A scalar (dup'd via ALU), B natural col-pairs.
// Epilogue staged through smem -> coalesced float2 global stores.
template<int K, int BN, bool RELU>
__global__ __launch_bounds__(32 * (BN / 10))
void gemm_f2(const float* __restrict__ A, const float* __restrict__ B,
             const float* __restrict__ bias, float* __restrict__ C,
             long M, int N) {
    constexpr int BM = 256;
    constexpr int NC = BN / 10;
    constexpr int THREADS = 32 * NC;
    constexpr int AS = BM + 3;           // 259, odd-ish stride: conflict-free STS
    extern __shared__ float sm[];
    float* Asm = sm;                     // [K][AS]
    float* Bsm = sm + K * AS;            // [K][BN]
    float* stg = Bsm + K * BN;           // [64][BN]

    const int tid = threadIdx.x;
    const int tc = tid / 32, tr = tid % 32;
    const long row0 = (long)blockIdx.y * BM;
    const int  col0 = blockIdx.x * BN;

    for (int i = tid; i < BM * K; i += THREADS) {
        int r = i / K, k = i - r * K;
        long gr = row0 + r;
        Asm[k * AS + r] = (gr < M) ? A[gr * (long)K + k] : 0.f;
    }
    for (int i = tid; i < K * BN; i += THREADS) {
        int k = i / BN, n = i - k * BN;
        Bsm[i] = B[(size_t)k * N + col0 + n];
    }
    __syncthreads();

    const int cbase = tc * 10;
    ull acc[8][5];
    #pragma unroll
    for (int j = 0; j < 8; j++)
        #pragma unroll
        for (int p = 0; p < 5; p++) acc[j][p] = 0ull;

    #pragma unroll 2
    for (int k = 0; k < K; k++) {
        ull bv[5];
        #pragma unroll
        for (int p = 0; p < 5; p++)
            bv[p] = *reinterpret_cast<const ull*>(&Bsm[k * BN + cbase + 2 * p]);
        const float* ar = &Asm[k * AS + tr];
        #pragma unroll
        for (int j = 0; j < 8; j++) {
            float a = ar[j * 32];
            ull ad = pk2(a, a);
            #pragma unroll
            for (int p = 0; p < 5; p++) fma2(acc[j][p], ad, bv[p]);
        }
    }

    float bl[5], bh[5];
    #pragma unroll
    for (int p = 0; p < 5; p++) {
        bl[p] = bias[col0 + cbase + 2 * p];
        bh[p] = bias[col0 + cbase + 2 * p + 1];
    }

    #pragma unroll 1
    for (int ch = 0; ch < 4; ch++) {
        __syncthreads();
        #pragma unroll
        for (int jj = 0; jj < 2; jj++) {
            int j = ch * 2 + jj;
            int rl = jj * 32 + tr;
            #pragma unroll
            for (int p = 0; p < 5; p++) {
                float lo, hi;
                upk2(acc[j][p], lo, hi);
                lo += bl[p]; hi += bh[p];
                if (RELU) { lo = fmaxf(lo, 0.f); hi = fmaxf(hi, 0.f); }
                *reinterpret_cast<float2*>(&stg[rl * BN + cbase + 2 * p]) =
                    make_float2(lo, hi);
            }
        }
        __syncthreads();
        for (int i = tid; i < 64 * (BN / 2); i += THREADS) {
            int r = i / (BN / 2), c2 = i - r * (BN / 2);
            long gr = row0 + ch * 64 + r;
            if (gr < M)
                *reinterpret_cast<float2*>(&C[gr * (size_t)N + col0 + 2 * c2]) =
                    *reinterpret_cast<const float2*>(&stg[r * BN + 2 * c2]);
        }
    }
}

// ---------------- 5x5 SAME conv, register-row reuse over kj -----------------
// Block = 3 images, 256 threads (234 active: img x 13 rows x 6 co-groups).
// smem: zero-padded transposed input [3][30ci][17r][18c] + weights [25][30][30].
// Thread: acc[7 col-pairs][5 co]; per (ci,ki) loads 18-wide row once (9 LDS.64)
// reused across kj via register pair extraction.
__global__ __launch_bounds__(256, 1)
void conv5x5_f2(const float* __restrict__ in, const float* __restrict__ w,
                const float* __restrict__ bias, float* __restrict__ out) {
    extern __shared__ float sm[];
    float* sin = sm;            // 3*30*306 = 27540 floats (also epilogue stage)
    float* sw  = sm + 27540;    // 22500 floats

    const int tid  = threadIdx.x;
    const int img0 = blockIdx.x * 3;

    for (int i = tid; i < 27540; i += 256) sin[i] = 0.f;
    for (int i = tid; i < 22500; i += 256) sw[i] = w[i];
    __syncthreads();
    for (int i = tid; i < 3 * 5070; i += 256) {
        int img = i / 5070, rem = i - img * 5070;
        if (img0 + img < NIMG) {
            int p = rem / 30, ci = rem - p * 30;
            sin[img * 9180 + ci * 306 + (p / 13 + 2) * 18 + (p % 13 + 2)] =
                in[(size_t)(img0 + img) * 5070 + rem];
        }
    }
    __syncthreads();

    const int img  = tid / 78;
    const int rr   = tid - img * 78;
    const int orow = rr / 6;
    const int cog  = rr - orow * 6;
    const int co0  = cog * 5;
    const bool on  = (tid < 234);

    ull acc[7][5];
    #pragma unroll
    for (int p = 0; p < 7; p++)
        #pragma unroll
        for (int c = 0; c < 5; c++) acc[p][c] = 0ull;

    if (on) {
        const float* bi = sin + img * 9180;
        #pragma unroll 1
        for (int ci = 0; ci < 30; ci++) {
            const float* bci = bi + ci * 306;
            #pragma unroll 1
            for (int ki = 0; ki < 5; ki++) {
                const float* vrow = bci + (orow + ki) * 18;
                float v[18];
                #pragma unroll
                for (int q = 0; q < 9; q++) {
                    float2 t2 = *reinterpret_cast<const float2*>(&vrow[2 * q]);
                    v[2 * q] = t2.x; v[2 * q + 1] = t2.y;
                }
                #pragma unroll
                for (int kj = 0; kj < 5; kj++) {
                    const float* wp = sw + ((ki * 5 + kj) * 30 + ci) * 30 + co0;
                    ull wd[5];
                    #pragma unroll
                    for (int c = 0; c < 5; c++) {
                        float wv = wp[c];
                        wd[c] = pk2(wv, wv);
                    }
                    #pragma unroll
                    for (int p = 0; p < 7; p++) {
                        ull a = pk2(v[2 * p + kj], v[2 * p + kj + 1]);
                        #pragma unroll
                        for (int c = 0; c < 5; c++) fma2(acc[p][c], a, wd[c]);
                    }
                }
            }
        }
    }

    __syncthreads();   // all reads of sin done; reuse as output stage
    if (on) {
        float bv[5];
        #pragma unroll
        for (int c = 0; c < 5; c++) bv[c] = bias[co0 + c];
        float* so = sin + img * 5070 + orow * 13 * 30 + co0;
        #pragma unroll
        for (int p = 0; p < 7; p++) {
            #pragma unroll
            for (int c = 0; c < 5; c++) {
                float lo, hi;
                upk2(acc[p][c], lo, hi);
                so[(2 * p) * 30 + c] = fmaxf(lo + bv[c], 0.f);
                if (p < 6) so[(2 * p + 1) * 30 + c] = fmaxf(hi + bv[c], 0.f);
            }
        }
    }
    __syncthreads();
    for (int i = tid; i < 3 * 5070; i += 256) {
        int img2 = i / 5070;
        if (img0 + img2 < NIMG)
            out[(size_t)(img0 + img2) * 5070 + (i - img2 * 5070)] = sin[i];
    }
}

// ---------------- persistent LSTM: all 55 timesteps in one kernel -----------
// Recurrence is row-local -> each block owns 74 rows, iterates t with only a
// block-level sync. Wh (160KB) loaded to smem ONCE; c in registers; h double-
// buffered transposed in smem (stride 83 to dodge bank conflicts).
#define SHP 83
__global__ __launch_bounds__(512, 1)
void lstm_persist(const float* __restrict__ xw, const float* __restrict__ Wh,
                  float* __restrict__ hs) {
    extern __shared__ float sm[];
    float* sW = sm;              // [100][400]
    float* sh = sm + 40000;      // 2 x [100][SHP]
    const int tid  = threadIdx.x;
    const int row0 = blockIdx.x * 74;

    for (int i = tid; i < 40000; i += 512) sW[i] = Wh[i];
    for (int i = tid; i < 2 * 100 * SHP; i += 512) sh[i] = 0.f;
    __syncthreads();

    const int ut = tid % 50;     // lanes span units -> coalesced gmem
    const int rt = tid / 50;
    const int u0 = 2 * ut;
    const bool on = tid < 500;

    int  rowg[8];
    bool val[8];
    #pragma unroll
    for (int j = 0; j < 8; j++) {
        int r = rt * 8 + j;
        rowg[j] = row0 + r;
        val[j] = on && (r < 74) && (rowg[j] < NN);
    }
    float cc[8][2];
    #pragma unroll
    for (int j = 0; j < 8; j++) { cc[j][0] = 0.f; cc[j][1] = 0.f; }

    int cur = 0;
    for (int t = 0; t < TSTEPS; t++) {
        const float* xwt = xw + (size_t)t * NN * 400;
        ull acc[8][4];
        #pragma unroll
        for (int j = 0; j < 8; j++) {
            if (val[j]) {
                const float* zr = xwt + (size_t)rowg[j] * 400 + u0;
                #pragma unroll
                for (int g = 0; g < 4; g++)
                    acc[j][g] = *reinterpret_cast<const ull*>(zr + g * 100);
            } else {
                #pragma unroll
                for (int g = 0; g < 4; g++) acc[j][g] = 0ull;
            }
        }

        if (t > 0) {
            const float* shc = sh + cur * (100 * SHP);
            const int rb = rt * 8;
            #pragma unroll 2
            for (int k = 0; k < 100; k++) {
                const float* wk = sW + k * 400 + u0;
                ull wq0 = *reinterpret_cast<const ull*>(wk);
                ull wq1 = *reinterpret_cast<const ull*>(wk + 100);
                ull wq2 = *reinterpret_cast<const ull*>(wk + 200);
                ull wq3 = *reinterpret_cast<const ull*>(wk + 300);
                const float* hv = shc + k * SHP + rb;
                #pragma unroll
                for (int j = 0; j < 8; j++) {
                    float av = hv[j];
                    ull ad = pk2(av, av);
                    fma2(acc[j][0], ad, wq0);
                    fma2(acc[j][1], ad, wq1);
                    fma2(acc[j][2], ad, wq2);
                    fma2(acc[j][3], ad, wq3);
                }
            }
        }

        float* shn = sh + (cur ^ 1) * (100 * SHP);
        float* hst = hs + (size_t)t * NN * HL;
        #pragma unroll
        for (int j = 0; j < 8; j++) {
            int r = rt * 8 + j;
            if (on && r < 74) {
                float i0, i1, j0, j1, f0, f1, o0, o1;
                upk2(acc[j][0], i0, i1);
                upk2(acc[j][1], j0, j1);
                upk2(acc[j][2], f0, f1);
                upk2(acc[j][3], o0, o1);
                float c0 = sigm(f0 + 1.f) * cc[j][0] + sigm(i0) * tanha(j0);
                float c1 = sigm(f1 + 1.f) * cc[j][1] + sigm(i1) * tanha(j1);
                cc[j][0] = c0; cc[j][1] = c1;
                float h0 = sigm(o0) * tanha(c0);
                float h1 = sigm(o1) * tanha(c1);
                shn[u0 * SHP + r]       = h0;
                shn[(u0 + 1) * SHP + r] = h1;
                if (rowg[j] < NN)
                    *reinterpret_cast<float2*>(&hst[(size_t)rowg[j] * HL + u0]) =
                        make_float2(h0, h1);
            }
        }
        cur ^= 1;
        __syncthreads();
    }
}

// ---------------- final 1x1 conv (100 -> 1) + output transpose --------------
__global__ void final_proj(const float* __restrict__ hs2, const float* __restrict__ we,
                           const float* __restrict__ be, float* __restrict__ out) {
    long r = (long)blockIdx.x * blockDim.x + threadIdx.x;
    if (r >= (long)NROWS) return;
    int n = (int)(r % NN);
    int l = (int)(r / NN);
    const float4* row = reinterpret_cast<const float4*>(hs2 + (size_t)r * HL);
    const float4* wv  = reinterpret_cast<const float4*>(we);
    float acc = 0.f;
    #pragma unroll
    for (int i = 0; i < 25; i++) {
        float4 v = row[i], w = wv[i];
        acc += v.x * w.x + v.y * w.y + v.z * w.z + v.w * w.w;
    }
    out[(size_t)n * 55 + l] = acc + be[0];
}

// ---------------- host side -------------------------------------------------
static inline size_t gsm(int K, int BN) {
    return (size_t)(K * 259 + K * BN + 64 * BN) * sizeof(float);
}

extern "C" void kernel_launch(void* const* d_in, const int* in_sizes, int n_in,
                              void* d_out, int out_size) {
    (void)in_sizes; (void)n_in; (void)out_size;
    const float* x = (const float*)d_in[0];
    const float* w1[4] = {(const float*)d_in[1], (const float*)d_in[3],
                          (const float*)d_in[5], (const float*)d_in[7]};
    const float* b1[4] = {(const float*)d_in[2], (const float*)d_in[4],
                          (const float*)d_in[6], (const float*)d_in[8]};
    const float* w2[4] = {(const float*)d_in[9],  (const float*)d_in[11],
                          (const float*)d_in[13], (const float*)d_in[15]};
    const float* b2[4] = {(const float*)d_in[10], (const float*)d_in[12],
                          (const float*)d_in[14], (const float*)d_in[16]};
    const float* lw1 = (const float*)d_in[17];
    const float* lb1 = (const float*)d_in[18];
    const float* lw2 = (const float*)d_in[19];
    const float* lb2 = (const float*)d_in[20];
    const float* we  = (const float*)d_in[21];
    const float* be  = (const float*)d_in[22];
    float* out = (float*)d_out;

    void *p0, *p1, *pxw, *ph1, *ph2;
    cudaGetSymbolAddress(&p0,  g_act0);
    cudaGetSymbolAddress(&p1,  g_act1);
    cudaGetSymbolAddress(&pxw, g_xw);
    cudaGetSymbolAddress(&ph1, g_hs1);
    cudaGetSymbolAddress(&ph2, g_hs2);
    float* act0 = (float*)p0;
    float* act1 = (float*)p1;
    float* xw   = (float*)pxw;
    float* hs1  = (float*)ph1;
    float* hs2  = (float*)ph2;

    const size_t conv_sm = 50040u * sizeof(float);                  // 200160
    const size_t lstm_sm = (40000u + 2u * 100u * SHP) * sizeof(float); // 226400
    cudaFuncSetAttribute(conv5x5_f2, cudaFuncAttributeMaxDynamicSharedMemorySize,
                         (int)conv_sm);
    cudaFuncSetAttribute(lstm_persist, cudaFuncAttributeMaxDynamicSharedMemorySize,
                         (int)lstm_sm);
    cudaFuncSetAttribute((const void*)gemm_f2<30, 100, false>,
                         cudaFuncAttributeMaxDynamicSharedMemorySize, (int)gsm(30, 100));
    cudaFuncSetAttribute((const void*)gemm_f2<100, 100, false>,
                         cudaFuncAttributeMaxDynamicSharedMemorySize, (int)gsm(100, 100));

    const unsigned GY = (NROWS + 255) / 256;   // 2324

    // 1) input transpose
    {
        long total = (long)NROWS * 6;
        transpose_in<<<(unsigned)((total + 255) / 256), 256>>>(x, act0);
    }

    // 2) four 1x1 convs (BN=30, 96 threads, 3 blocks/SM)
    gemm_f2<24, 30, true><<<dim3(1, GY), 96, gsm(24, 30)>>>(act0, w1[0], b1[0], act1, NROWS, 30);
    gemm_f2<30, 30, true><<<dim3(1, GY), 96, gsm(30, 30)>>>(act1, w1[1], b1[1], act0, NROWS, 30);
    gemm_f2<30, 30, true><<<dim3(1, GY), 96, gsm(30, 30)>>>(act0, w1[2], b1[2], act1, NROWS, 30);
    gemm_f2<30, 30, true><<<dim3(1, GY), 96, gsm(30, 30)>>>(act1, w1[3], b1[3], act0, NROWS, 30);

    // 3) four 5x5 SAME convs
    {
        const int grid = (NIMG + 2) / 3;   // 1174
        conv5x5_f2<<<grid, 256, conv_sm>>>(act0, w2[0], b2[0], act1);
        conv5x5_f2<<<grid, 256, conv_sm>>>(act1, w2[1], b2[1], act0);
        conv5x5_f2<<<grid, 256, conv_sm>>>(act0, w2[2], b2[2], act1);
        conv5x5_f2<<<grid, 256, conv_sm>>>(act1, w2[3], b2[3], act0);
    }

    // 4) LSTM layer 1: bulk x-projection then persistent recurrence
    gemm_f2<30, 100, false><<<dim3(4, GY), 320, gsm(30, 100)>>>(act0, lw1, lb1, xw, NROWS, 400);
    lstm_persist<<<147, 512, lstm_sm>>>(xw, lw1 + (size_t)30 * 400, hs1);

    //    LSTM layer 2
    gemm_f2<100, 100, false><<<dim3(4, GY), 320, gsm(100, 100)>>>(hs1, lw2, lb2, xw, NROWS, 400);
    lstm_persist<<<147, 512, lstm_sm>>>(xw, lw2 + (size_t)100 * 400, hs2);

    // 5) final projection + output transpose
    final_proj<<<(NROWS + 255) / 256, 256>>>(hs2, we, be, out);
}

// round 5
// speedup vs baseline: 1.5782x; 1.1180x over previous
#include <cuda_runtime.h>
#include <cstdint>

#define NROWS 594880   // 55 * 64 * 169
#define NN    10816    // 64 * 169 rows per timestep
#define TSTEPS 55
#define HL    100
#define NIMG  3520     // 55 * 64 images of 13x13

typedef unsigned long long ull;

// ---------------- f32x2 packed-math helpers (sm_103a FFMA2) -----------------
__device__ __forceinline__ ull pk2(float lo, float hi) {
    ull r; asm("mov.b64 %0,{%1,%2};" : "=l"(r) : "f"(lo), "f"(hi)); return r;
}
__device__ __forceinline__ void upk2(ull v, float& lo, float& hi) {
    asm("mov.b64 {%0,%1},%2;" : "=f"(lo), "=f"(hi) : "l"(v));
}
__device__ __forceinline__ void fma2(ull& d, ull a, ull b) {
    asm("fma.rn.f32x2 %0,%1,%2,%3;" : "=l"(d) : "l"(a), "l"(b), "l"(d));
}

__device__ __forceinline__ float sigm(float x) {
    return __fdividef(1.f, 1.f + __expf(-x));
}
__device__ __forceinline__ float tanha(float x) {
    return __fdividef(2.f, 1.f + __expf(-2.f * x)) - 1.f;
}

// ---------------- static device scratch -------------------------------------
__device__ float g_act0[(size_t)NROWS * 30];
__device__ float g_act1[(size_t)NROWS * 30];
__device__ float g_xw [(size_t)NROWS * 400];
__device__ float g_hs1[(size_t)NROWS * HL];
__device__ float g_hs2[(size_t)NROWS * HL];

// ---------------- input transpose: [B,13,13,L,C] -> [(l*64+b)*169+pix, 24] --
__global__ void transpose_in(const float* __restrict__ x, float* __restrict__ y) {
    long idx = (long)blockIdx.x * blockDim.x + threadIdx.x;
    const long total = (long)NROWS * 6;
    if (idx >= total) return;
    int  c4  = (int)(idx % 6);
    long row = idx / 6;
    int  pix = (int)(row % 169);
    long t1  = row / 169;
    int  b   = (int)(t1 % 64);
    int  l   = (int)(t1 / 64);
    long src = (((long)(b * 169 + pix)) * 55 + l) * 24 + c4 * 4;
    reinterpret_cast<float4*>(y)[row * 6 + c4] =
        *reinterpret_cast<const float4*>(x + src);
}

// ---------------- fused 1x1 conv chain: 4 layers, activations in registers --
// 128 threads, 2 rows/thread (256 rows/block). Weights for all 4 layers in
// smem, broadcast LDS.64 col-pairs (even offsets only). Stage smem (stride 33,
// SCALAR access only) for coalesced entry load / exit store.
#define C1_STG 33
__global__ __launch_bounds__(128, 3)
void conv1_fused(const float* __restrict__ A,
                 const float* __restrict__ w0, const float* __restrict__ b0,
                 const float* __restrict__ w1, const float* __restrict__ b1,
                 const float* __restrict__ w2, const float* __restrict__ b2,
                 const float* __restrict__ w3, const float* __restrict__ b3,
                 float* __restrict__ Cout, long M) {
    extern __shared__ float sm[];
    float* stage = sm;                 // [256][33], scalar access only
    float* sw    = sm + 256 * C1_STG;  // 720 + 3*900 = 3420 (base even: 8448)
    float* sb    = sw + 3420;          // 4 x 30

    const int tid  = threadIdx.x;
    const long row0 = (long)blockIdx.x * 256;

    for (int i = tid; i < 720; i += 128) sw[i] = w0[i];
    for (int i = tid; i < 900; i += 128) {
        sw[720 + i]  = w1[i];
        sw[1620 + i] = w2[i];
        sw[2520 + i] = w3[i];
    }
    if (tid < 30) {
        sb[tid] = b0[tid]; sb[30 + tid] = b1[tid];
        sb[60 + tid] = b2[tid]; sb[90 + tid] = b3[tid];
    }
    // coalesced input load: 256 rows x 24 = 1536 float4 (gmem aligned)
    for (int f = tid; f < 1536; f += 128) {
        int r = f / 6, c4 = f - r * 6;
        long gr = row0 + r;
        float4 v = make_float4(0.f, 0.f, 0.f, 0.f);
        if (gr < M) v = *reinterpret_cast<const float4*>(A + gr * 24 + 4 * c4);
        float* d = &stage[r * C1_STG + 4 * c4];
        d[0] = v.x; d[1] = v.y; d[2] = v.z; d[3] = v.w;
    }
    __syncthreads();

    float a0[30], a1[30];
    {
        const float* s0 = &stage[(2 * tid) * C1_STG];
        const float* s1 = &stage[(2 * tid + 1) * C1_STG];
        #pragma unroll
        for (int k = 0; k < 24; k++) { a0[k] = s0[k]; a1[k] = s1[k]; }
    }

    ull acc0[15], acc1[15];
    #pragma unroll 1
    for (int layer = 0; layer < 4; layer++) {
        const int K = (layer == 0) ? 24 : 30;
        const float* wl = sw + ((layer == 0) ? 0 : 720 + (layer - 1) * 900);
        const float* bl = sb + layer * 30;
        #pragma unroll
        for (int p = 0; p < 15; p++) { acc0[p] = 0ull; acc1[p] = 0ull; }
        #pragma unroll 6
        for (int k = 0; k < K; k++) {
            ull ad0 = pk2(a0[k], a0[k]);
            ull ad1 = pk2(a1[k], a1[k]);
            const ull* wk = reinterpret_cast<const ull*>(&wl[k * 30]);  // even offs
            #pragma unroll
            for (int p = 0; p < 15; p++) {
                ull bv = wk[p];
                fma2(acc0[p], ad0, bv);
                fma2(acc1[p], ad1, bv);
            }
        }
        #pragma unroll
        for (int p = 0; p < 15; p++) {
            float l0, h0, l1, h1;
            upk2(acc0[p], l0, h0);
            upk2(acc1[p], l1, h1);
            float be = bl[2 * p], bo = bl[2 * p + 1];
            a0[2 * p]     = fmaxf(l0 + be, 0.f);
            a0[2 * p + 1] = fmaxf(h0 + bo, 0.f);
            a1[2 * p]     = fmaxf(l1 + be, 0.f);
            a1[2 * p + 1] = fmaxf(h1 + bo, 0.f);
        }
    }

    __syncthreads();   // all threads done reading stage -> reuse for output
    {
        float* s0 = &stage[(2 * tid) * C1_STG];
        float* s1 = &stage[(2 * tid + 1) * C1_STG];
        #pragma unroll
        for (int k = 0; k < 30; k++) { s0[k] = a0[k]; s1[k] = a1[k]; }
    }
    __syncthreads();
    // coalesced output store (gmem float2 aligned: row stride 30 even)
    for (int f = tid; f < 256 * 15; f += 128) {
        int r = f / 15, c2 = f - r * 15;
        long gr = row0 + r;
        if (gr < M) {
            const float* s = &stage[r * C1_STG + 2 * c2];
            *reinterpret_cast<float2*>(&Cout[gr * 30 + 2 * c2]) =
                make_float2(s[0], s[1]);
        }
    }
}

// ---------------- bulk LSTM x-projection GEMM: C = A[M,K]@B[K,400] + bias ---
// BM=128, BN=100 (grid.x=4), 320 threads, 4 rows x 5 col-pairs per thread.
// B loads warp-uniform (broadcast, even offsets). Stage aliases smem base
// post-sync; stride 101, SCALAR access only.
template<int K>
__global__ __launch_bounds__(320, 2)
void gemm_xw(const float* __restrict__ A, const float* __restrict__ B,
             const float* __restrict__ bias, float* __restrict__ C, long M) {
    constexpr int BM = 128, BN = 100, AS = BM + 3;   // 131
    extern __shared__ float sm[];
    float* Asm = sm;                 // [K][AS]
    float* Bsm = sm + K * AS;        // [K][BN]  (base even: K*131 even)
    float* stg = sm;                 // alias (post-sync), stride 101, scalar

    const int tid = threadIdx.x;
    const int tc = tid / 32, tr = tid % 32;
    const long row0 = (long)blockIdx.y * BM;
    const int  col0 = blockIdx.x * BN;

    for (int i = tid; i < BM * K; i += 320) {
        int r = i / K, k = i - r * K;
        long gr = row0 + r;
        Asm[k * AS + r] = (gr < M) ? A[gr * (long)K + k] : 0.f;
    }
    for (int i = tid; i < K * BN; i += 320) {
        int k = i / BN, n = i - k * BN;
        Bsm[i] = B[(size_t)k * 400 + col0 + n];
    }
    __syncthreads();

    const int cbase = tc * 10;
    ull acc[4][5];
    #pragma unroll
    for (int j = 0; j < 4; j++)
        #pragma unroll
        for (int p = 0; p < 5; p++) acc[j][p] = 0ull;

    #pragma unroll 5
    for (int k = 0; k < K; k++) {
        ull bv[5];
        #pragma unroll
        for (int p = 0; p < 5; p++)
            bv[p] = *reinterpret_cast<const ull*>(&Bsm[k * BN + cbase + 2 * p]);
        const float* ar = &Asm[k * AS + tr];
        #pragma unroll
        for (int j = 0; j < 4; j++) {
            float a = ar[32 * j];
            ull ad = pk2(a, a);
            #pragma unroll
            for (int p = 0; p < 5; p++) fma2(acc[j][p], ad, bv[p]);
        }
    }

    float bl[5], bh[5];
    #pragma unroll
    for (int p = 0; p < 5; p++) {
        bl[p] = bias[col0 + cbase + 2 * p];
        bh[p] = bias[col0 + cbase + 2 * p + 1];
    }

    #pragma unroll 1
    for (int ch = 0; ch < 2; ch++) {
        __syncthreads();
        #pragma unroll
        for (int jj = 0; jj < 2; jj++) {
            int j = ch * 2 + jj;
            int rl = jj * 32 + tr;
            float* sr = &stg[rl * 101 + cbase];
            #pragma unroll
            for (int p = 0; p < 5; p++) {
                float lo, hi;
                upk2(acc[j][p], lo, hi);
                sr[2 * p]     = lo + bl[p];
                sr[2 * p + 1] = hi + bh[p];
            }
        }
        __syncthreads();
        for (int i = tid; i < 64 * 50; i += 320) {
            int r = i / 50, c2 = i - r * 50;
            long gr = row0 + ch * 64 + r;
            if (gr < M) {
                const float* s = &stg[r * 101 + 2 * c2];
                *reinterpret_cast<float2*>(&C[gr * 400 + col0 + 2 * c2]) =
                    make_float2(s[0], s[1]);
            }
        }
    }
}

// ---------------- 5x5 SAME conv, precomputed aligned/shifted pixel pairs ----
__global__ __launch_bounds__(256, 1)
void conv5x5_f2(const float* __restrict__ in, const float* __restrict__ w,
                const float* __restrict__ bias, float* __restrict__ out) {
    extern __shared__ float sm[];
    float* sin = sm;            // 3*30*306 = 27540 floats (also epilogue stage)
    float* sw  = sm + 27540;    // 22500 floats

    const int tid  = threadIdx.x;
    const int img0 = blockIdx.x * 3;

    for (int i = tid; i < 27540; i += 256) sin[i] = 0.f;
    for (int i = tid; i < 22500; i += 256) sw[i] = w[i];
    __syncthreads();
    for (int i = tid; i < 3 * 5070; i += 256) {
        int img = i / 5070, rem = i - img * 5070;
        if (img0 + img < NIMG) {
            int p = rem / 30, ci = rem - p * 30;
            sin[img * 9180 + ci * 306 + (p / 13 + 2) * 18 + (p % 13 + 2)] =
                in[(size_t)(img0 + img) * 5070 + rem];
        }
    }
    __syncthreads();

    const int img  = tid / 78;
    const int rr   = tid - img * 78;
    const int orow = rr / 6;
    const int cog  = rr - orow * 6;
    const int co0  = cog * 5;
    const bool on  = (tid < 234);

    ull acc[7][5];
    #pragma unroll
    for (int p = 0; p < 7; p++)
        #pragma unroll
        for (int c = 0; c < 5; c++) acc[p][c] = 0ull;

    if (on) {
        const float* bi = sin + img * 9180;
        #pragma unroll 1
        for (int ci = 0; ci < 30; ci++) {
            const float* bci = bi + ci * 306;
            #pragma unroll 1
            for (int ki = 0; ki < 5; ki++) {
                const float* vrow = bci + (orow + ki) * 18;   // even offsets
                float2 t[9];
                #pragma unroll
                for (int q = 0; q < 9; q++)
                    t[q] = *reinterpret_cast<const float2*>(&vrow[2 * q]);
                ull va[9], vs[8];
                #pragma unroll
                for (int q = 0; q < 9; q++) va[q] = pk2(t[q].x, t[q].y);
                #pragma unroll
                for (int p = 0; p < 8; p++) vs[p] = pk2(t[p].y, t[p + 1].x);
                #pragma unroll
                for (int kj = 0; kj < 5; kj++) {
                    const float* wp = sw + ((ki * 5 + kj) * 30 + ci) * 30 + co0;
                    ull wd[5];
                    #pragma unroll
                    for (int c = 0; c < 5; c++) {
                        float wv = wp[c];
                        wd[c] = pk2(wv, wv);
                    }
                    #pragma unroll
                    for (int p = 0; p < 7; p++) {
                        ull a = (kj == 0) ? va[p] :
                                (kj == 1) ? vs[p] :
                                (kj == 2) ? va[p + 1] :
                                (kj == 3) ? vs[p + 1] : va[p + 2];
                        #pragma unroll
                        for (int c = 0; c < 5; c++) fma2(acc[p][c], a, wd[c]);
                    }
                }
            }
        }
    }

    __syncthreads();   // all reads of sin done; reuse as output stage
    if (on) {
        float bv[5];
        #pragma unroll
        for (int c = 0; c < 5; c++) bv[c] = bias[co0 + c];
        float* so = sin + img * 5070 + orow * 13 * 30 + co0;
        #pragma unroll
        for (int p = 0; p < 7; p++) {
            #pragma unroll
            for (int c = 0; c < 5; c++) {
                float lo, hi;
                upk2(acc[p][c], lo, hi);
                so[(2 * p) * 30 + c] = fmaxf(lo + bv[c], 0.f);
                if (p < 6) so[(2 * p + 1) * 30 + c] = fmaxf(hi + bv[c], 0.f);
            }
        }
    }
    __syncthreads();
    for (int i = tid; i < 3 * 5070; i += 256) {
        int img2 = i / 5070;
        if (img0 + img2 < NIMG)
            out[(size_t)(img0 + img2) * 5070 + (i - img2 * 5070)] = sin[i];
    }
}

// ---------------- persistent LSTM: all 55 timesteps in one kernel -----------
#define SHP 82
__global__ __launch_bounds__(512, 1)
void lstm_persist(const float* __restrict__ xw, const float* __restrict__ Wh,
                  float* __restrict__ hs) {
    extern __shared__ float sm[];
    float* sW = sm;              // [100][400]
    float* sh = sm + 40000;      // 2 x [100][SHP]
    const int tid  = threadIdx.x;
    const int row0 = blockIdx.x * 74;

    for (int i = tid; i < 40000; i += 512) sW[i] = Wh[i];
    for (int i = tid; i < 2 * 100 * SHP; i += 512) sh[i] = 0.f;
    __syncthreads();

    const int ut = tid % 50;
    const int rt = tid / 50;
    const int u0 = 2 * ut;
    const bool on = tid < 500;

    int  rowg[8];
    bool val[8];
    #pragma unroll
    for (int j = 0; j < 8; j++) {
        int r = rt * 8 + j;
        rowg[j] = row0 + r;
        val[j] = on && (r < 74) && (rowg[j] < NN);
    }
    float cc[8][2];
    #pragma unroll
    for (int j = 0; j < 8; j++) { cc[j][0] = 0.f; cc[j][1] = 0.f; }

    int cur = 0;
    for (int t = 0; t < TSTEPS; t++) {
        const float* xwt = xw + (size_t)t * NN * 400;
        ull acc[8][4];
        #pragma unroll
        for (int j = 0; j < 8; j++) {
            if (val[j]) {
                const float* zr = xwt + (size_t)rowg[j] * 400 + u0;
                #pragma unroll
                for (int g = 0; g < 4; g++)
                    acc[j][g] = *reinterpret_cast<const ull*>(zr + g * 100);
            } else {
                #pragma unroll
                for (int g = 0; g < 4; g++) acc[j][g] = 0ull;
            }
        }

        if (t > 0) {
            const float* shc = sh + cur * (100 * SHP);
            const int rb = rt * 8;
            #pragma unroll 2
            for (int k = 0; k < 100; k++) {
                const float* wk = sW + k * 400 + u0;
                ull wq0 = *reinterpret_cast<const ull*>(wk);
                ull wq1 = *reinterpret_cast<const ull*>(wk + 100);
                ull wq2 = *reinterpret_cast<const ull*>(wk + 200);
                ull wq3 = *reinterpret_cast<const ull*>(wk + 300);
                const float* hv = shc + k * SHP + rb;   // even offsets
                ull hp[4];
                #pragma unroll
                for (int q = 0; q < 4; q++)
                    hp[q] = *reinterpret_cast<const ull*>(&hv[2 * q]);
                #pragma unroll
                for (int q = 0; q < 4; q++) {
                    float he, ho;
                    upk2(hp[q], he, ho);
                    ull ade = pk2(he, he);
                    fma2(acc[2 * q][0], ade, wq0);
                    fma2(acc[2 * q][1], ade, wq1);
                    fma2(acc[2 * q][2], ade, wq2);
                    fma2(acc[2 * q][3], ade, wq3);
                    ull ado = pk2(ho, ho);
                    fma2(acc[2 * q + 1][0], ado, wq0);
                    fma2(acc[2 * q + 1][1], ado, wq1);
                    fma2(acc[2 * q + 1][2], ado, wq2);
                    fma2(acc[2 * q + 1][3], ado, wq3);
                }
            }
        }

        float* shn = sh + (cur ^ 1) * (100 * SHP);
        float* hst = hs + (size_t)t * NN * HL;
        #pragma unroll
        for (int j = 0; j < 8; j++) {
            int r = rt * 8 + j;
            if (on && r < 74) {
                float i0, i1, j0, j1, f0, f1, o0, o1;
                upk2(acc[j][0], i0, i1);
                upk2(acc[j][1], j0, j1);
                upk2(acc[j][2], f0, f1);
                upk2(acc[j][3], o0, o1);
                float c0 = sigm(f0 + 1.f) * cc[j][0] + sigm(i0) * tanha(j0);
                float c1 = sigm(f1 + 1.f) * cc[j][1] + sigm(i1) * tanha(j1);
                cc[j][0] = c0; cc[j][1] = c1;
                float h0 = sigm(o0) * tanha(c0);
                float h1 = sigm(o1) * tanha(c1);
                shn[u0 * SHP + r]       = h0;
                shn[(u0 + 1) * SHP + r] = h1;
                if (rowg[j] < NN)
                    *reinterpret_cast<float2*>(&hst[(size_t)rowg[j] * HL + u0]) =
                        make_float2(h0, h1);
            }
        }
        cur ^= 1;
        __syncthreads();
    }
}

// ---------------- final 1x1 conv (100 -> 1) + output transpose --------------
__global__ void final_proj(const float* __restrict__ hs2, const float* __restrict__ we,
                           const float* __restrict__ be, float* __restrict__ out) {
    long r = (long)blockIdx.x * blockDim.x + threadIdx.x;
    if (r >= (long)NROWS) return;
    int n = (int)(r % NN);
    int l = (int)(r / NN);
    const float4* row = reinterpret_cast<const float4*>(hs2 + (size_t)r * HL);
    const float4* wv  = reinterpret_cast<const float4*>(we);
    float acc = 0.f;
    #pragma unroll
    for (int i = 0; i < 25; i++) {
        float4 v = row[i], w = wv[i];
        acc += v.x * w.x + v.y * w.y + v.z * w.z + v.w * w.w;
    }
    out[(size_t)n * 55 + l] = acc + be[0];
}

// ---------------- host side -------------------------------------------------
extern "C" void kernel_launch(void* const* d_in, const int* in_sizes, int n_in,
                              void* d_out, int out_size) {
    (void)in_sizes; (void)n_in; (void)out_size;
    const float* x = (const float*)d_in[0];
    const float* w1[4] = {(const float*)d_in[1], (const float*)d_in[3],
                          (const float*)d_in[5], (const float*)d_in[7]};
    const float* b1[4] = {(const float*)d_in[2], (const float*)d_in[4],
                          (const float*)d_in[6], (const float*)d_in[8]};
    const float* w2[4] = {(const float*)d_in[9],  (const float*)d_in[11],
                          (const float*)d_in[13], (const float*)d_in[15]};
    const float* b2[4] = {(const float*)d_in[10], (const float*)d_in[12],
                          (const float*)d_in[14], (const float*)d_in[16]};
    const float* lw1 = (const float*)d_in[17];
    const float* lb1 = (const float*)d_in[18];
    const float* lw2 = (const float*)d_in[19];
    const float* lb2 = (const float*)d_in[20];
    const float* we  = (const float*)d_in[21];
    const float* be  = (const float*)d_in[22];
    float* out = (float*)d_out;

    void *p0, *p1, *pxw, *ph1, *ph2;
    cudaGetSymbolAddress(&p0,  g_act0);
    cudaGetSymbolAddress(&p1,  g_act1);
    cudaGetSymbolAddress(&pxw, g_xw);
    cudaGetSymbolAddress(&ph1, g_hs1);
    cudaGetSymbolAddress(&ph2, g_hs2);
    float* act0 = (float*)p0;
    float* act1 = (float*)p1;
    float* xw   = (float*)pxw;
    float* hs1  = (float*)ph1;
    float* hs2  = (float*)ph2;

    const size_t conv_sm  = 50040u * sizeof(float);                   // 200160
    const size_t lstm_sm  = (40000u + 2u * 100u * SHP) * sizeof(float); // 225600
    const size_t c1_sm    = (256u * C1_STG + 3420u + 120u) * sizeof(float); // 47952
    const size_t g30_sm   = (size_t)(30 * 231) * sizeof(float);       // 27720
    const size_t g100_sm  = (size_t)(100 * 231) * sizeof(float);      // 92400

    cudaFuncSetAttribute(conv5x5_f2, cudaFuncAttributeMaxDynamicSharedMemorySize,
                         (int)conv_sm);
    cudaFuncSetAttribute(lstm_persist, cudaFuncAttributeMaxDynamicSharedMemorySize,
                         (int)lstm_sm);
    cudaFuncSetAttribute((const void*)gemm_xw<100>,
                         cudaFuncAttributeMaxDynamicSharedMemorySize, (int)g100_sm);

    // 1) input transpose
    {
        long total = (long)NROWS * 6;
        transpose_in<<<(unsigned)((total + 255) / 256), 256>>>(x, act0);
    }

    // 2) fused 1x1 conv chain (4 layers, one kernel)
    {
        const unsigned grid = (NROWS + 255) / 256;   // 2324
        conv1_fused<<<grid, 128, c1_sm>>>(act0,
                                          w1[0], b1[0], w1[1], b1[1],
                                          w1[2], b1[2], w1[3], b1[3],
                                          act1, NROWS);
    }

    // 3) four 5x5 SAME convs
    {
        const int grid = (NIMG + 2) / 3;   // 1174
        conv5x5_f2<<<grid, 256, conv_sm>>>(act1, w2[0], b2[0], act0);
        conv5x5_f2<<<grid, 256, conv_sm>>>(act0, w2[1], b2[1], act1);
        conv5x5_f2<<<grid, 256, conv_sm>>>(act1, w2[2], b2[2], act0);
        conv5x5_f2<<<grid, 256, conv_sm>>>(act0, w2[3], b2[3], act1);
    }

    const unsigned GY = (NROWS + 127) / 128;   // 4648

    // 4) LSTM layer 1
    gemm_xw<30><<<dim3(4, GY), 320, g30_sm>>>(act1, lw1, lb1, xw, NROWS);
    lstm_persist<<<147, 512, lstm_sm>>>(xw, lw1 + (size_t)30 * 400, hs1);

    //    LSTM layer 2
    gemm_xw<100><<<dim3(4, GY), 320, g100_sm>>>(hs1, lw2, lb2, xw, NROWS);
    lstm_persist<<<147, 512, lstm_sm>>>(xw, lw2 + (size_t)100 * 400, hs2);

    // 5) final projection + output transpose
    final_proj<<<(NROWS + 255) / 256, 256>>>(hs2, we, be, out);
}